// round 8
// baseline (speedup 1.0000x reference)
#include <cuda_runtime.h>
#include <math.h>

// ---------------------------------------------------------------------------
// 2-layer LSTM (T=1024, B=128, E=58, H=256) + Linear(256->33) + softplus.
//
// Strategy: persistent per-layer kernel, 128 CTAs (16 hidden-slices x 8
// batch-slices). Each CTA keeps its weight slice W[4*16 rows][K] in SMEM for
// all 1024 timesteps. Cell state c lives in registers (each CTA owns the
// (b,h) tile whose gates it computes, so c never leaves the SM). h history is
// written to the y[t] buffer, which doubles as the h_{t-1} source — no extra
// double buffer and no WAR hazard. One atomic grid barrier per step
// (all 128 CTAs are co-resident: 1 CTA/SM by smem, grid <= 148 SMs).
// ---------------------------------------------------------------------------

namespace {
constexpr int TT = 1024;
constexpr int BB = 128;
constexpr int EE = 58;
constexpr int HH = 256;
constexpr int OO = 33;

constexpr int HT = 16;                 // hidden units per CTA
constexpr int BT = 16;                 // batch per CTA
constexpr int HS = HH / HT;            // 16 hidden slices
constexpr int BS = BB / BT;            // 8 batch slices
constexpr int NCTA = HS * BS;          // 128
constexpr int NTHR = 256;
constexpr int KSPLIT = 4;              // k-split across thread groups
constexpr int WS_STRIDE = 4 * HT;      // 64 gate-columns per CTA
constexpr int IN_STRIDE = BT + 4;      // 20: pad, keeps float4 align (80B) + spreads banks
constexpr int PART_STRIDE = BT + 1;    // 17: pad to kill bank conflicts
constexpr int PART_SZ = 4 * HT * PART_STRIDE;  // 1088 floats per k-group
}

// Scratch (static __device__: allocation-free per harness rules)
__device__ float g_y0[(size_t)TT * HH * BB];   // layer0 outputs, [t][h][b]
__device__ float g_y1[(size_t)TT * HH * BB];   // layer1 outputs, [t][h][b]
__device__ unsigned g_bar[2];                  // per-layer barrier counters

__global__ void reset_kernel() {
    g_bar[0] = 0u;
    g_bar[1] = 0u;
}

template<int LAYER>
__global__ void __launch_bounds__(NTHR, 1)
lstm_layer_kernel(const float* __restrict__ xin,   // LAYER0: x [T][B][E] (unused for LAYER1)
                  const float* __restrict__ W_ih,  // (4H, K1) row-major
                  const float* __restrict__ W_hh,  // (4H, H)  row-major
                  const float* __restrict__ b_ih,
                  const float* __restrict__ b_hh,
                  const float* __restrict__ h0,    // (B, H) this layer's slice
                  const float* __restrict__ c0,    // (B, H)
                  float* __restrict__ hn,          // (B, H)
                  float* __restrict__ cn)          // (B, H)
{
    constexpr int K1   = (LAYER == 0) ? EE : HH;   // input-projection K
    constexpr int KTOT = K1 + HH;                  // concatenated [x_t ; h_{t-1}]

    float*       yout = (LAYER == 0) ? g_y0 : g_y1;
    const float* xsrc = (LAYER == 0) ? xin  : g_y0;
    unsigned*    barp = &g_bar[LAYER];

    extern __shared__ float sm[];
    float* Ws   = sm;                                  // [KTOT][WS_STRIDE]
    float* In   = Ws + KTOT * WS_STRIDE;               // [KTOT][IN_STRIDE]
    float* Part = In + KTOT * IN_STRIDE;               // [KSPLIT][PART_SZ]

    const int tid   = threadIdx.x;
    const int cta   = blockIdx.x;
    const int hsl   = cta & (HS - 1);
    const int bsl   = cta >> 4;
    const int hbase = hsl * HT;
    const int bbase = bsl * BT;

    // ---- stage weight slice once (transpose to [k][gate*16+hh]) ----
    for (int i = tid; i < KTOT * WS_STRIDE; i += NTHR) {
        int jl = i / KTOT;
        int k  = i - jl * KTOT;
        int gate = jl >> 4;
        int hh   = jl & 15;
        int row  = gate * HH + hbase + hh;
        float w = (k < K1) ? W_ih[row * K1 + k] : W_hh[row * HH + (k - K1)];
        Ws[k * WS_STRIDE + jl] = w;
    }

    // ---- compute-thread mapping: (kgroup, bt, jt), 4x4 acc tile ----
    const int kg = tid >> 6;         // 0..3
    const int rr = tid & 63;
    const int bt = rr >> 4;          // 0..3
    const int jt = rr & 15;          // 0..15
    const int kbeg = (KTOT * kg) / KSPLIT;
    const int kend = (KTOT * (kg + 1)) / KSPLIT;
    const int kn = kend - kbeg;

    // ---- epilogue-thread mapping: (eb, eh) owns one (b, h) cell ----
    const int eb = tid >> 4;         // 0..15
    const int eh = tid & 15;         // 0..15
    const float bias0 = b_ih[0 * HH + hbase + eh] + b_hh[0 * HH + hbase + eh];
    const float bias1 = b_ih[1 * HH + hbase + eh] + b_hh[1 * HH + hbase + eh];
    const float bias2 = b_ih[2 * HH + hbase + eh] + b_hh[2 * HH + hbase + eh];
    const float bias3 = b_ih[3 * HH + hbase + eh] + b_hh[3 * HH + hbase + eh];
    float cacc = c0[(bbase + eb) * HH + hbase + eh];

    __syncthreads();

    for (int t = 0; t < TT; t++) {
        // ---- grid barrier: wait until all CTAs finished step t-1 ----
        if (t > 0) {
            if (tid == 0) {
                const unsigned target = (unsigned)t * NCTA;
                unsigned v;
                do {
                    asm volatile("ld.acquire.gpu.u32 %0, [%1];" : "=r"(v) : "l"(barp));
                } while (v < target);
            }
            __syncthreads();
        }

        // ---- stage inputs In[k][b]: [x_t ; h_{t-1}] for our batch tile ----
        if (LAYER == 0) {
            const float* xt = xsrc + (size_t)t * BB * EE;   // [B][E]
            for (int i = tid; i < EE * BT; i += NTHR) {
                int b = i / EE;
                int k = i - b * EE;
                In[k * IN_STRIDE + b] = xt[(bbase + b) * EE + k];
            }
        } else {
            const float* xt = xsrc + (size_t)t * HH * BB;   // y0[t]: [H][B]
            for (int i = tid; i < HH * BT; i += NTHR) {
                int k = i >> 4;
                int b = i & 15;
                In[k * IN_STRIDE + b] = xt[k * BB + bbase + b];
            }
        }
        if (t == 0) {
            for (int i = tid; i < HH * BT; i += NTHR) {
                int k = i >> 4;
                int b = i & 15;
                In[(K1 + k) * IN_STRIDE + b] = h0[(bbase + b) * HH + k];
            }
        } else {
            const float* hp = yout + (size_t)(t - 1) * HH * BB;  // own h history
            for (int i = tid; i < HH * BT; i += NTHR) {
                int k = i >> 4;
                int b = i & 15;
                In[(K1 + k) * IN_STRIDE + b] = hp[k * BB + bbase + b];
            }
        }
        __syncthreads();

        // ---- GEMM partial: 16 FMAs per k, LDS well under 128B/cyc ----
        float4 acc0 = {0.f, 0.f, 0.f, 0.f};
        float4 acc1 = acc0, acc2 = acc0, acc3 = acc0;
        const float* wp = Ws + kbeg * WS_STRIDE + jt * 4;
        const float* ip = In + kbeg * IN_STRIDE + bt * 4;
        #pragma unroll 4
        for (int k = 0; k < kn; k++) {
            const float4 w = *reinterpret_cast<const float4*>(wp);
            const float4 h = *reinterpret_cast<const float4*>(ip);
            acc0.x += h.x * w.x; acc0.y += h.x * w.y; acc0.z += h.x * w.z; acc0.w += h.x * w.w;
            acc1.x += h.y * w.x; acc1.y += h.y * w.y; acc1.z += h.y * w.z; acc1.w += h.y * w.w;
            acc2.x += h.z * w.x; acc2.y += h.z * w.y; acc2.z += h.z * w.z; acc2.w += h.z * w.w;
            acc3.x += h.w * w.x; acc3.y += h.w * w.y; acc3.z += h.w * w.z; acc3.w += h.w * w.w;
            wp += WS_STRIDE;
            ip += IN_STRIDE;
        }

        {
            float* pb = Part + kg * PART_SZ + (jt * 4) * PART_STRIDE + bt * 4;
            pb[0] = acc0.x; pb[1] = acc1.x; pb[2] = acc2.x; pb[3] = acc3.x; pb += PART_STRIDE;
            pb[0] = acc0.y; pb[1] = acc1.y; pb[2] = acc2.y; pb[3] = acc3.y; pb += PART_STRIDE;
            pb[0] = acc0.z; pb[1] = acc1.z; pb[2] = acc2.z; pb[3] = acc3.z; pb += PART_STRIDE;
            pb[0] = acc0.w; pb[1] = acc1.w; pb[2] = acc2.w; pb[3] = acc3.w;
        }
        __syncthreads();

        // ---- epilogue: reduce k-groups, gate math, update c (register) ----
        float si = bias0, sf = bias1, sg = bias2, so = bias3;
        #pragma unroll
        for (int p = 0; p < KSPLIT; p++) {
            const float* pp = Part + p * PART_SZ + eb;
            si += pp[(0 * HT + eh) * PART_STRIDE];
            sf += pp[(1 * HT + eh) * PART_STRIDE];
            sg += pp[(2 * HT + eh) * PART_STRIDE];
            so += pp[(3 * HT + eh) * PART_STRIDE];
        }
        const float ig = 1.f / (1.f + __expf(-si));
        const float fg = 1.f / (1.f + __expf(-sf));
        const float gt = tanhf(sg);
        const float og = 1.f / (1.f + __expf(-so));
        cacc = fg * cacc + ig * gt;
        const float hv = og * tanhf(cacc);

        yout[(size_t)t * HH * BB + (hbase + eh) * BB + (bbase + eb)] = hv;
        if (t == TT - 1) {
            hn[(bbase + eb) * HH + hbase + eh] = hv;
            cn[(bbase + eb) * HH + hbase + eh] = cacc;
        }

        // ---- arrive: publish our h tile for step t ----
        __threadfence();
        __syncthreads();
        if (tid == 0) atomicAdd(barp, 1u);
    }
}

// Final projection + softplus: out[t][b][o] = softplus(y1[t]·W_out^T + b_out)
__global__ void __launch_bounds__(128, 4)
proj_kernel(const float* __restrict__ W_out,  // (33, 256)
            const float* __restrict__ b_out,  // (33,)
            float* __restrict__ out)          // [T][B][33]
{
    __shared__ float Wsm[HH * OO];   // [k][o]
    const int t = blockIdx.x;
    const int b = threadIdx.x;       // 0..127

    for (int i = b; i < HH * OO; i += 128) {
        int k = i / OO;
        int o = i - k * OO;
        Wsm[k * OO + o] = W_out[o * HH + k];
    }
    __syncthreads();

    const float* y = g_y1 + (size_t)t * HH * BB;   // [H][B]
    float acc[OO];
    #pragma unroll
    for (int o = 0; o < OO; o++) acc[o] = b_out[o];

    for (int k = 0; k < HH; k++) {
        const float yv = y[k * BB + b];            // coalesced across the warp
        const float* wr = &Wsm[k * OO];
        #pragma unroll
        for (int o = 0; o < OO; o++) acc[o] += yv * wr[o];
    }

    float* op = out + (size_t)t * BB * OO + b * OO;
    #pragma unroll
    for (int o = 0; o < OO; o++) {
        const float x = acc[o];
        op[o] = fmaxf(x, 0.f) + log1pf(__expf(-fabsf(x)));  // stable softplus
    }
}

extern "C" void kernel_launch(void* const* d_in, const int* in_sizes, int n_in,
                              void* d_out, int out_size) {
    const float* x     = (const float*)d_in[0];
    const float* h0    = (const float*)d_in[1];   // (2,B,H)
    const float* c0    = (const float*)d_in[2];   // (2,B,H)
    const float* W_ih0 = (const float*)d_in[3];
    const float* W_hh0 = (const float*)d_in[4];
    const float* b_ih0 = (const float*)d_in[5];
    const float* b_hh0 = (const float*)d_in[6];
    const float* W_ih1 = (const float*)d_in[7];
    const float* W_hh1 = (const float*)d_in[8];
    const float* b_ih1 = (const float*)d_in[9];
    const float* b_hh1 = (const float*)d_in[10];
    const float* W_out = (const float*)d_in[11];
    const float* b_out = (const float*)d_in[12];

    float* out = (float*)d_out;
    float* hn  = out + (size_t)TT * BB * OO;   // (2,B,H)
    float* cn  = hn + 2 * BB * HH;             // (2,B,H)

    constexpr int KTOT0 = EE + HH;   // 314
    constexpr int KTOT1 = HH + HH;   // 512
    const int smem0 = (KTOT0 * WS_STRIDE + KTOT0 * IN_STRIDE + KSPLIT * PART_SZ) * 4; // ~123 KB
    const int smem1 = (KTOT1 * WS_STRIDE + KTOT1 * IN_STRIDE + KSPLIT * PART_SZ) * 4; // ~189 KB

    cudaFuncSetAttribute((const void*)lstm_layer_kernel<0>,
                         cudaFuncAttributeMaxDynamicSharedMemorySize, smem0);
    cudaFuncSetAttribute((const void*)lstm_layer_kernel<1>,
                         cudaFuncAttributeMaxDynamicSharedMemorySize, smem1);

    reset_kernel<<<1, 1>>>();

    lstm_layer_kernel<0><<<NCTA, NTHR, smem0>>>(
        x, W_ih0, W_hh0, b_ih0, b_hh0,
        h0 + 0 * BB * HH, c0 + 0 * BB * HH,
        hn + 0 * BB * HH, cn + 0 * BB * HH);

    lstm_layer_kernel<1><<<NCTA, NTHR, smem1>>>(
        nullptr, W_ih1, W_hh1, b_ih1, b_hh1,
        h0 + 1 * BB * HH, c0 + 1 * BB * HH,
        hn + 1 * BB * HH, cn + 1 * BB * HH);

    proj_kernel<<<TT, 128>>>(W_out, b_out, out);
}

// round 9
// speedup vs baseline: 1.2152x; 1.2152x over previous
#include <cuda_runtime.h>
#include <math.h>
#include <stdint.h>

// ---------------------------------------------------------------------------
// 2-layer LSTM (T=1024, B=128, E=58, H=256) + Linear(256->33) + softplus.
//
// R9 changes vs R8:
//  * Barrier: per-CTA flags (single writer, st.release / ld.acquire on
//    distinct addresses, group-local: only the 16 CTAs sharing a batch slice
//    synchronize). Removes the 128-way single-address atomic serialization
//    (~3.5K cyc/step) and the gpu-scope threadfence.
//  * GEMM: fma.rn.f32x2 (FFMA2) — accumulators paired over adjacent gate
//    columns. Ws float4 loads give the weight pairs for free; In is stored
//    PRE-DUPLICATED (h,h) as float2 so the broadcast pairs are free too.
//    Zero pack instructions: per k per thread = 3 LDS.128 + 8 FFMA2 (32 MACs).
//  * Latency hiding: x-part GEMM (independent of h[t-1]) runs BEFORE the
//    flag poll, so the inter-CTA publish latency is shadowed.
// ---------------------------------------------------------------------------

namespace {
constexpr int TT = 1024;
constexpr int BB = 128;
constexpr int EE = 58;
constexpr int HH = 256;
constexpr int OO = 33;

constexpr int HT = 16;              // hidden units per CTA
constexpr int BT = 16;              // batch per CTA
constexpr int HS = HH / HT;         // 16 hidden slices
constexpr int BS = BB / BT;         // 8 batch slices
constexpr int NCTA = HS * BS;       // 128
constexpr int NTHR = 256;
constexpr int WS_COLS = 4 * HT;     // 64 gate columns per CTA
constexpr int BSTR2 = 18;           // float2 per In row (16 + pad, even for 16B align)
constexpr int PART_J = 68;          // padded j-stride in Part (mult of 4)
}

// Scratch (static __device__: allocation-free per harness rules)
__device__ float g_y0[(size_t)TT * HH * BB];   // layer0 outputs, [t][h][b]
__device__ float g_y1[(size_t)TT * HH * BB];   // layer1 outputs, [t][h][b]
__device__ unsigned g_flags[2 * NCTA];         // per-layer, per-CTA step counters

__global__ void reset_kernel() {
    int i = threadIdx.x;
    if (i < 2 * NCTA) g_flags[i] = 0u;
}

__device__ __forceinline__ void ffma2(uint64_t& d, uint64_t a, uint64_t b) {
    asm("fma.rn.f32x2 %0, %1, %2, %0;" : "+l"(d) : "l"(a), "l"(b));
}

template<int LAYER>
__global__ void __launch_bounds__(NTHR, 1)
lstm_layer_kernel(const float* __restrict__ xin,   // LAYER0: x [T][B][E]
                  const float* __restrict__ W_ih,  // (4H, K1) row-major
                  const float* __restrict__ W_hh,  // (4H, H)  row-major
                  const float* __restrict__ b_ih,
                  const float* __restrict__ b_hh,
                  const float* __restrict__ h0,    // (B, H) this layer's slice
                  const float* __restrict__ c0,    // (B, H)
                  float* __restrict__ hn,          // (B, H)
                  float* __restrict__ cn)          // (B, H)
{
    constexpr int K1   = (LAYER == 0) ? EE : HH;   // input-projection K
    constexpr int KTOT = K1 + HH;                  // [x_t ; h_{t-1}]

    float*       yout = (LAYER == 0) ? g_y0 : g_y1;
    const float* xsrc = (LAYER == 0) ? xin  : g_y0;

    extern __shared__ float sm[];
    float*  Ws   = sm;                                        // [KTOT][64]
    float2* In2  = (float2*)(sm + KTOT * WS_COLS);            // [KTOT][BSTR2], (v,v) dup
    float*  Part = (float*)(In2 + KTOT * BSTR2);              // [4][BT][PART_J]

    const int tid   = threadIdx.x;
    const int cta   = blockIdx.x;
    const int hsl   = cta & (HS - 1);
    const int bsl   = cta >> 4;
    const int hbase = hsl * HT;
    const int bbase = bsl * BT;

    // ---- stage weight slice once: Ws[k][gate*16+hh] ----
    for (int i = tid; i < KTOT * WS_COLS; i += NTHR) {
        int jl = i / KTOT;
        int k  = i - jl * KTOT;
        int gate = jl >> 4;
        int hh   = jl & 15;
        int row  = gate * HH + hbase + hh;
        float w = (k < K1) ? W_ih[row * K1 + k] : W_hh[row * HH + (k - K1)];
        Ws[k * WS_COLS + jl] = w;
    }

    // ---- compute-thread mapping ----
    const int kg = tid >> 6;          // 0..3  (k-split group)
    const int rr = tid & 63;
    const int bt = rr >> 4;           // 0..3  (4 batch each)
    const int jt = rr & 15;           // 0..15 (4 gate-cols each, 2 pairs)
    const int xb = (K1 * kg) / 4;     // x-part k-range
    const int xe = (K1 * (kg + 1)) / 4;
    const int hb = K1 + kg * (HH / 4);  // h-part k-range
    const int he = hb + HH / 4;

    // ---- epilogue mapping: (eb, eh) owns one (b, h) cell ----
    const int eb = tid >> 4;
    const int eh = tid & 15;
    const float bias0 = b_ih[0 * HH + hbase + eh] + b_hh[0 * HH + hbase + eh];
    const float bias1 = b_ih[1 * HH + hbase + eh] + b_hh[1 * HH + hbase + eh];
    const float bias2 = b_ih[2 * HH + hbase + eh] + b_hh[2 * HH + hbase + eh];
    const float bias3 = b_ih[3 * HH + hbase + eh] + b_hh[3 * HH + hbase + eh];
    float cacc = c0[(bbase + eb) * HH + hbase + eh];

    const unsigned* flg_grp = &g_flags[LAYER * NCTA + bsl * HS];
    unsigned* flg_self = &g_flags[LAYER * NCTA + cta];

    __syncthreads();

    for (int t = 0; t < TT; t++) {
        // ---- Phase A: stage x-part of In (independent of h[t-1]) ----
        if (LAYER == 0) {
            const float* xt = xsrc + (size_t)t * BB * EE;   // [B][E]
            for (int i = tid; i < EE * BT; i += NTHR) {
                int b = i / EE;
                int k = i - b * EE;
                float v = xt[(bbase + b) * EE + k];
                In2[k * BSTR2 + b] = make_float2(v, v);
            }
        } else {
            const float* xt = xsrc + (size_t)t * HH * BB;   // y0[t]: [H][B]
            for (int i = tid; i < HH * BT; i += NTHR) {
                int k = i >> 4;
                int b = i & 15;
                float v = xt[k * BB + bbase + b];
                In2[k * BSTR2 + b] = make_float2(v, v);
            }
        }
        __syncthreads();   // S1

        // ---- x-part GEMM (shadows the inter-CTA publish latency) ----
        uint64_t acc[2][4] = {{0ull,0ull,0ull,0ull},{0ull,0ull,0ull,0ull}};
        {
            const ulonglong2* Wp = reinterpret_cast<const ulonglong2*>(Ws) + (size_t)xb * 16 + jt;
            const ulonglong2* Ip = reinterpret_cast<const ulonglong2*>(In2) + (size_t)xb * 9 + bt * 2;
            const int n = xe - xb;
            #pragma unroll 2
            for (int k = 0; k < n; k++) {
                const ulonglong2 w = Wp[(size_t)k * 16];
                const ulonglong2 a = Ip[(size_t)k * 9];
                const ulonglong2 b = Ip[(size_t)k * 9 + 1];
                ffma2(acc[0][0], w.x, a.x); ffma2(acc[1][0], w.y, a.x);
                ffma2(acc[0][1], w.x, a.y); ffma2(acc[1][1], w.y, a.y);
                ffma2(acc[0][2], w.x, b.x); ffma2(acc[1][2], w.y, b.x);
                ffma2(acc[0][3], w.x, b.y); ffma2(acc[1][3], w.y, b.y);
            }
        }

        // ---- group-local barrier: wait for the 16 producers of our bsl ----
        if (t > 0) {
            if (tid < HS) {
                const unsigned* fp = flg_grp + tid;
                unsigned v;
                do {
                    asm volatile("ld.acquire.gpu.global.u32 %0, [%1];" : "=r"(v) : "l"(fp));
                } while (v < (unsigned)t);
            }
            __syncthreads();   // S2
        }

        // ---- stage h-part of In ----
        if (t == 0) {
            for (int i = tid; i < HH * BT; i += NTHR) {
                int k = i >> 4;
                int b = i & 15;
                float v = h0[(bbase + b) * HH + k];
                In2[(K1 + k) * BSTR2 + b] = make_float2(v, v);
            }
        } else {
            const float* hp = yout + (size_t)(t - 1) * HH * BB;  // [H][B]
            for (int i = tid; i < HH * BT; i += NTHR) {
                int k = i >> 4;
                int b = i & 15;
                float v = hp[k * BB + bbase + b];
                In2[(K1 + k) * BSTR2 + b] = make_float2(v, v);
            }
        }
        __syncthreads();   // S3

        // ---- h-part GEMM ----
        {
            const ulonglong2* Wp = reinterpret_cast<const ulonglong2*>(Ws) + (size_t)hb * 16 + jt;
            const ulonglong2* Ip = reinterpret_cast<const ulonglong2*>(In2) + (size_t)hb * 9 + bt * 2;
            #pragma unroll 4
            for (int k = 0; k < HH / 4; k++) {
                const ulonglong2 w = Wp[(size_t)k * 16];
                const ulonglong2 a = Ip[(size_t)k * 9];
                const ulonglong2 b = Ip[(size_t)k * 9 + 1];
                ffma2(acc[0][0], w.x, a.x); ffma2(acc[1][0], w.y, a.x);
                ffma2(acc[0][1], w.x, a.y); ffma2(acc[1][1], w.y, a.y);
                ffma2(acc[0][2], w.x, b.x); ffma2(acc[1][2], w.y, b.x);
                ffma2(acc[0][3], w.x, b.y); ffma2(acc[1][3], w.y, b.y);
            }
        }

        // ---- write partials: Part[kg][b][j], 16B-aligned vector stores ----
        {
            float* pb = Part + kg * (BT * PART_J) + jt * 4;
            #pragma unroll
            for (int i = 0; i < 4; i++) {
                ulonglong2 v;
                v.x = acc[0][i];
                v.y = acc[1][i];
                *reinterpret_cast<ulonglong2*>(pb + (bt * 4 + i) * PART_J) = v;
            }
        }
        __syncthreads();   // S4

        // ---- epilogue: reduce k-groups, gate math, update c (register) ----
        float si = bias0, sf = bias1, sg = bias2, so = bias3;
        #pragma unroll
        for (int p = 0; p < 4; p++) {
            const float* pp = Part + p * (BT * PART_J) + eb * PART_J;
            si += pp[0 * HT + eh];
            sf += pp[1 * HT + eh];
            sg += pp[2 * HT + eh];
            so += pp[3 * HT + eh];
        }
        const float ig = 1.f / (1.f + __expf(-si));
        const float fg = 1.f / (1.f + __expf(-sf));
        const float gt = tanhf(sg);
        const float og = 1.f / (1.f + __expf(-so));
        cacc = fg * cacc + ig * gt;
        const float hv = og * tanhf(cacc);

        yout[(size_t)t * HH * BB + (hbase + eh) * BB + (bbase + eb)] = hv;
        if (t == TT - 1) {
            hn[(bbase + eb) * HH + hbase + eh] = hv;
            cn[(bbase + eb) * HH + hbase + eh] = cacc;
        }

        __syncthreads();   // S5: all hv stores done
        if (tid == 0) {
            asm volatile("st.release.gpu.global.u32 [%0], %1;"
                         :: "l"(flg_self), "r"((unsigned)(t + 1)) : "memory");
        }
    }
}

// Final projection + softplus: out[t][b][o] = softplus(y1[t]·W_out^T + b_out)
__global__ void __launch_bounds__(128, 4)
proj_kernel(const float* __restrict__ W_out,  // (33, 256)
            const float* __restrict__ b_out,  // (33,)
            float* __restrict__ out)          // [T][B][33]
{
    __shared__ float Wsm[HH * OO];   // [k][o]
    const int t = blockIdx.x;
    const int b = threadIdx.x;       // 0..127

    for (int i = b; i < HH * OO; i += 128) {
        int k = i / OO;
        int o = i - k * OO;
        Wsm[k * OO + o] = W_out[o * HH + k];
    }
    __syncthreads();

    const float* y = g_y1 + (size_t)t * HH * BB;   // [H][B]
    float acc[OO];
    #pragma unroll
    for (int o = 0; o < OO; o++) acc[o] = b_out[o];

    #pragma unroll 4
    for (int k = 0; k < HH; k++) {
        const float yv = y[k * BB + b];            // coalesced across the warp
        const float* wr = &Wsm[k * OO];
        #pragma unroll
        for (int o = 0; o < OO; o++) acc[o] += yv * wr[o];
    }

    float* op = out + (size_t)t * BB * OO + b * OO;
    #pragma unroll
    for (int o = 0; o < OO; o++) {
        const float x = acc[o];
        op[o] = fmaxf(x, 0.f) + log1pf(__expf(-fabsf(x)));  // stable softplus
    }
}

extern "C" void kernel_launch(void* const* d_in, const int* in_sizes, int n_in,
                              void* d_out, int out_size) {
    const float* x     = (const float*)d_in[0];
    const float* h0    = (const float*)d_in[1];   // (2,B,H)
    const float* c0    = (const float*)d_in[2];   // (2,B,H)
    const float* W_ih0 = (const float*)d_in[3];
    const float* W_hh0 = (const float*)d_in[4];
    const float* b_ih0 = (const float*)d_in[5];
    const float* b_hh0 = (const float*)d_in[6];
    const float* W_ih1 = (const float*)d_in[7];
    const float* W_hh1 = (const float*)d_in[8];
    const float* b_ih1 = (const float*)d_in[9];
    const float* b_hh1 = (const float*)d_in[10];
    const float* W_out = (const float*)d_in[11];
    const float* b_out = (const float*)d_in[12];

    float* out = (float*)d_out;
    float* hn  = out + (size_t)TT * BB * OO;   // (2,B,H)
    float* cn  = hn + 2 * BB * HH;             // (2,B,H)

    constexpr int KTOT0 = EE + HH;   // 314
    constexpr int KTOT1 = HH + HH;   // 512
    const int smem0 = KTOT0 * WS_COLS * 4 + KTOT0 * BSTR2 * 8 + 4 * BT * PART_J * 4; // 143008 B
    const int smem1 = KTOT1 * WS_COLS * 4 + KTOT1 * BSTR2 * 8 + 4 * BT * PART_J * 4; // 222208 B

    cudaFuncSetAttribute((const void*)lstm_layer_kernel<0>,
                         cudaFuncAttributeMaxDynamicSharedMemorySize, smem0);
    cudaFuncSetAttribute((const void*)lstm_layer_kernel<1>,
                         cudaFuncAttributeMaxDynamicSharedMemorySize, smem1);

    reset_kernel<<<1, 256>>>();

    lstm_layer_kernel<0><<<NCTA, NTHR, smem0>>>(
        x, W_ih0, W_hh0, b_ih0, b_hh0,
        h0 + 0 * BB * HH, c0 + 0 * BB * HH,
        hn + 0 * BB * HH, cn + 0 * BB * HH);

    lstm_layer_kernel<1><<<NCTA, NTHR, smem1>>>(
        nullptr, W_ih1, W_hh1, b_ih1, b_hh1,
        h0 + 1 * BB * HH, c0 + 1 * BB * HH,
        hn + 1 * BB * HH, cn + 1 * BB * HH);

    proj_kernel<<<TT, 128>>>(W_out, b_out, out);
}

// round 10
// speedup vs baseline: 1.7505x; 1.4405x over previous
#include <cuda_runtime.h>
#include <math.h>
#include <stdint.h>

// ---------------------------------------------------------------------------
// 2-layer LSTM (T=1024, B=128, E=58, H=256) + Linear(256->33) + softplus.
//
// R10 vs R9:
//  * GEMM tile widened: 8 cols x 4 batch per thread (16 f32x2 accs),
//    KSPLIT=8 (warp == k-group). 4 LDS.128 per 16 FFMA2 (was 3 per 8),
//    and weight LDS is now 8x16B-consecutive -> conflict-free.
//  * h history stored PRE-DUPLICATED (v,v) in global: consumers stage h with
//    plain LDG.128 -> STS.128 copies.
//  * x for step t+1 prefetched into registers during step t's GEMMs.
//  * Part buffer aliased onto In2's dead x-region for layer 1 (exact 32KB).
//  * Fast gate math: __fdividef + exp-based tanh (~1e-6 err, margin is 1e-3).
// ---------------------------------------------------------------------------

namespace {
constexpr int TT = 1024;
constexpr int BB = 128;
constexpr int EE = 58;
constexpr int HH = 256;
constexpr int OO = 33;

constexpr int HT = 16;              // hidden units per CTA
constexpr int BT = 16;              // batch per CTA
constexpr int HS = HH / HT;         // 16 hidden slices
constexpr int BS = BB / BT;         // 8 batch slices
constexpr int NCTA = HS * BS;       // 128
constexpr int NTHR = 256;
}

// Scratch (static __device__: allocation-free per harness rules)
__device__ float2 g_y0[(size_t)TT * HH * BB];  // layer0 h, [t][h][b], (v,v) dup
__device__ float2 g_y1[(size_t)TT * HH * BB];  // layer1 h, [t][h][b], (v,v) dup
__device__ unsigned g_flags[2 * NCTA];

__global__ void reset_kernel() {
    int i = threadIdx.x;
    if (i < 2 * NCTA) g_flags[i] = 0u;
}

__device__ __forceinline__ void ffma2(uint64_t& d, uint64_t a, uint64_t b) {
    asm("fma.rn.f32x2 %0, %1, %2, %0;" : "+l"(d) : "l"(a), "l"(b));
}

__device__ __forceinline__ float fast_sigmoid(float x) {
    return __fdividef(1.f, 1.f + __expf(-x));
}
__device__ __forceinline__ float fast_tanh(float x) {
    float t = __expf(-2.f * fabsf(x));
    float r = __fdividef(1.f - t, 1.f + t);
    return copysignf(r, x);
}

// GEMM over k range [k0,k1): 8 cols x 4 batch per thread via f32x2.
__device__ __forceinline__ void gemm_range(const float* __restrict__ Ws,
                                           const float2* __restrict__ In2,
                                           int k0, int k1, int jt, int bt,
                                           uint64_t acc[4][4]) {
    const char* wp = (const char*)(Ws + (size_t)k0 * 64 + jt * 4);
    const char* ip = (const char*)(In2 + (size_t)k0 * 16 + bt * 4);
    #pragma unroll 4
    for (int k = k0; k < k1; k++) {
        const ulonglong2 wA = *(const ulonglong2*)wp;          // cols jt*4..+3
        const ulonglong2 wB = *(const ulonglong2*)(wp + 128);  // cols 32+jt*4..+3
        const ulonglong2 ia = *(const ulonglong2*)ip;          // b: bt*4+0,1 (dup)
        const ulonglong2 ib = *(const ulonglong2*)(ip + 16);   // b: bt*4+2,3
        ffma2(acc[0][0], wA.x, ia.x); ffma2(acc[1][0], wA.y, ia.x);
        ffma2(acc[2][0], wB.x, ia.x); ffma2(acc[3][0], wB.y, ia.x);
        ffma2(acc[0][1], wA.x, ia.y); ffma2(acc[1][1], wA.y, ia.y);
        ffma2(acc[2][1], wB.x, ia.y); ffma2(acc[3][1], wB.y, ia.y);
        ffma2(acc[0][2], wA.x, ib.x); ffma2(acc[1][2], wA.y, ib.x);
        ffma2(acc[2][2], wB.x, ib.x); ffma2(acc[3][2], wB.y, ib.x);
        ffma2(acc[0][3], wA.x, ib.y); ffma2(acc[1][3], wA.y, ib.y);
        ffma2(acc[2][3], wB.x, ib.y); ffma2(acc[3][3], wB.y, ib.y);
        wp += 256;
        ip += 128;
    }
}

template<int LAYER>
__global__ void __launch_bounds__(NTHR, 1)
lstm_layer_kernel(const float* __restrict__ xin,   // LAYER0 only: x [T][B][E]
                  const float* __restrict__ W_ih,  // (4H, K1) row-major
                  const float* __restrict__ W_hh,  // (4H, H)  row-major
                  const float* __restrict__ b_ih,
                  const float* __restrict__ b_hh,
                  const float* __restrict__ h0,    // (B, H)
                  const float* __restrict__ c0,    // (B, H)
                  float* __restrict__ hn,          // (B, H)
                  float* __restrict__ cn)          // (B, H)
{
    constexpr int K1   = (LAYER == 0) ? EE : HH;
    constexpr int KTOT = K1 + HH;

    float2*       yout = (LAYER == 0) ? g_y0 : g_y1;   // own h history (dup)
    const float2* xdup = g_y0;                          // LAYER1 x source

    extern __shared__ float sm[];
    float*  Ws  = sm;                                   // [KTOT][64]
    float2* In2 = (float2*)(sm + (size_t)KTOT * 64);    // [KTOT][16] dup pairs
    // Part: 8 kg x 16 b x 64 cols = 32768 B. L1: alias onto In2 x-region
    // (exactly 256 rows x 128 B). L0: separate tail region.
    float* Part = (LAYER == 1) ? (float*)In2
                               : (float*)(In2 + (size_t)KTOT * 16);

    const int tid   = threadIdx.x;
    const int cta   = blockIdx.x;
    const int hsl   = cta & (HS - 1);
    const int bsl   = cta >> 4;
    const int hbase = hsl * HT;
    const int bbase = bsl * BT;

    // ---- stage weight slice once: Ws[k][gate*16+hh] ----
    for (int i = tid; i < KTOT * 64; i += NTHR) {
        int jl = i / KTOT;
        int k  = i - jl * KTOT;
        int gate = jl >> 4;
        int hh   = jl & 15;
        int row  = gate * HH + hbase + hh;
        float w = (k < K1) ? W_ih[row * K1 + k] : W_hh[row * HH + (k - K1)];
        Ws[(size_t)k * 64 + jl] = w;
    }

    // ---- GEMM thread mapping: warp == k-group ----
    const int kg = tid >> 5;          // 0..7
    const int rr = tid & 31;
    const int bt = rr >> 3;           // 0..3 (4 batch)
    const int jt = rr & 7;            // 0..7 (cols jt*4..+3 and 32+jt*4..+3)
    const int kx0 = (K1 * kg) / 8;
    const int kx1 = (K1 * (kg + 1)) / 8;
    const int kh0 = K1 + kg * (HH / 8);
    const int kh1 = kh0 + HH / 8;

    // ---- dup-tile index map (h staging + L1 x staging): 8 uint4 each ----
    int    sIdx[8];
    size_t gIdx[8];
    #pragma unroll
    for (int m = 0; m < 8; m++) {
        int e = tid + m * 256;        // 0..2047
        int k = e >> 3;
        int bq = e & 7;
        sIdx[m] = k * 16 + bq * 2;                       // float2 idx in In2 rows
        gIdx[m] = (size_t)k * BB + bbase + bq * 2;       // float2 idx in y plane
    }

    // ---- L0 x scalar map: 4 elems per thread ----
    int  xsk[4], xsb[4], xgo[4];
    bool xok[4];
    if (LAYER == 0) {
        #pragma unroll
        for (int m = 0; m < 4; m++) {
            int idx = tid + m * 256;
            xok[m] = idx < EE * BT;
            int b = idx / EE;
            int k = idx - b * EE;
            xsk[m] = k; xsb[m] = b;
            xgo[m] = (bbase + b) * EE + k;
        }
    }

    // ---- epilogue mapping ----
    const int eb = tid >> 4;
    const int eh = tid & 15;
    const float bias0 = b_ih[0 * HH + hbase + eh] + b_hh[0 * HH + hbase + eh];
    const float bias1 = b_ih[1 * HH + hbase + eh] + b_hh[1 * HH + hbase + eh];
    const float bias2 = b_ih[2 * HH + hbase + eh] + b_hh[2 * HH + hbase + eh];
    const float bias3 = b_ih[3 * HH + hbase + eh] + b_hh[3 * HH + hbase + eh];
    float cacc = c0[(bbase + eb) * HH + hbase + eh];

    const unsigned* flg_grp = &g_flags[LAYER * NCTA + bsl * HS];
    unsigned* flg_self = &g_flags[LAYER * NCTA + cta];

    // ---- prologue x prefetch (t = 0) ----
    float xv[4];
    uint4 xr[8];
    if (LAYER == 0) {
        #pragma unroll
        for (int m = 0; m < 4; m++) xv[m] = xok[m] ? xin[xgo[m]] : 0.f;
    } else {
        #pragma unroll
        for (int m = 0; m < 8; m++)
            xr[m] = *(const uint4*)&xdup[gIdx[m]];
    }

    __syncthreads();

    for (int t = 0; t < TT; t++) {
        // ---- store x_t (from regs) into In2 x-region ----
        if (LAYER == 0) {
            #pragma unroll
            for (int m = 0; m < 4; m++)
                if (xok[m]) In2[xsk[m] * 16 + xsb[m]] = make_float2(xv[m], xv[m]);
        } else {
            #pragma unroll
            for (int m = 0; m < 8; m++)
                *(uint4*)&In2[sIdx[m]] = xr[m];
        }
        __syncthreads();   // S1

        // ---- prefetch x_{t+1} into regs (completes under the GEMMs) ----
        if (t + 1 < TT) {
            if (LAYER == 0) {
                const float* xt = xin + (size_t)(t + 1) * BB * EE;
                #pragma unroll
                for (int m = 0; m < 4; m++) if (xok[m]) xv[m] = xt[xgo[m]];
            } else {
                const float2* xp = xdup + (size_t)(t + 1) * HH * BB;
                #pragma unroll
                for (int m = 0; m < 8; m++) xr[m] = *(const uint4*)&xp[gIdx[m]];
            }
        }

        // ---- x-part GEMM (shadows peers' publish latency) ----
        uint64_t acc[4][4] = {{0,0,0,0},{0,0,0,0},{0,0,0,0},{0,0,0,0}};
        gemm_range(Ws, In2, kx0, kx1, jt, bt, acc);

        // ---- group-local barrier: 16 producers of our batch slice ----
        if (t > 0) {
            if (tid < HS) {
                const unsigned* fp = flg_grp + tid;
                unsigned v;
                do {
                    asm volatile("ld.acquire.gpu.global.u32 %0, [%1];" : "=r"(v) : "l"(fp));
                } while (v < (unsigned)t);
            }
            __syncthreads();   // S2
        }

        // ---- stage h_{t-1} (already dup in global) ----
        if (t == 0) {
            #pragma unroll
            for (int m = 0; m < 16; m++) {
                int idx = tid + m * 256;
                int k = idx >> 4;
                int b = idx & 15;
                float v = h0[(bbase + b) * HH + k];
                In2[(K1 + k) * 16 + b] = make_float2(v, v);
            }
        } else {
            const float2* hp = yout + (size_t)(t - 1) * HH * BB;
            #pragma unroll
            for (int m = 0; m < 8; m++) {
                uint4 v = *(const uint4*)&hp[gIdx[m]];
                *(uint4*)&In2[K1 * 16 + sIdx[m]] = v;
            }
        }
        __syncthreads();   // S3

        // ---- h-part GEMM ----
        gemm_range(Ws, In2, kh0, kh1, jt, bt, acc);

        // ---- write partials (aliases In2 x-region for LAYER1 — safe:
        //      x-GEMM done (S3), next x-store is after S5) ----
        {
            float* pb = Part + kg * 1024 + (bt * 4) * 64 + jt * 4;
            #pragma unroll
            for (int b = 0; b < 4; b++) {
                ulonglong2 vA; vA.x = acc[0][b]; vA.y = acc[1][b];
                ulonglong2 vB; vB.x = acc[2][b]; vB.y = acc[3][b];
                *(ulonglong2*)(pb + b * 64)      = vA;
                *(ulonglong2*)(pb + b * 64 + 32) = vB;
            }
        }
        __syncthreads();   // S4

        // ---- epilogue: reduce 8 k-groups, gate math, update c ----
        float s0 = bias0, s1 = bias1, s2 = bias2, s3 = bias3;
        #pragma unroll
        for (int p = 0; p < 8; p++) {
            const float* pp = Part + p * 1024 + eb * 64;
            s0 += pp[ 0 + eh];
            s1 += pp[16 + eh];
            s2 += pp[32 + eh];
            s3 += pp[48 + eh];
        }
        const float ig = fast_sigmoid(s0);
        const float fg = fast_sigmoid(s1);
        const float gt = fast_tanh(s2);
        const float og = fast_sigmoid(s3);
        cacc = fg * cacc + ig * gt;
        const float hv = og * fast_tanh(cacc);

        yout[(size_t)t * HH * BB + (hbase + eh) * BB + (bbase + eb)] =
            make_float2(hv, hv);
        if (t == TT - 1) {
            hn[(bbase + eb) * HH + hbase + eh] = hv;
            cn[(bbase + eb) * HH + hbase + eh] = cacc;
        }

        __syncthreads();   // S5: all hv stores + Part reads done
        if (tid == 0) {
            asm volatile("st.release.gpu.global.u32 [%0], %1;"
                         :: "l"(flg_self), "r"((unsigned)(t + 1)) : "memory");
        }
    }
}

// Final projection + softplus: out[t][b][o] = softplus(y1[t]·W_out^T + b_out)
__global__ void __launch_bounds__(128, 4)
proj_kernel(const float* __restrict__ W_out,  // (33, 256)
            const float* __restrict__ b_out,  // (33,)
            float* __restrict__ out)          // [T][B][33]
{
    __shared__ float Wsm[HH * OO];   // [k][o]
    const int t = blockIdx.x;
    const int b = threadIdx.x;       // 0..127

    for (int i = b; i < HH * OO; i += 128) {
        int k = i / OO;
        int o = i - k * OO;
        Wsm[k * OO + o] = W_out[o * HH + k];
    }
    __syncthreads();

    const float2* y = g_y1 + (size_t)t * HH * BB;   // [H][B] dup
    float acc[OO];
    #pragma unroll
    for (int o = 0; o < OO; o++) acc[o] = b_out[o];

    #pragma unroll 4
    for (int k = 0; k < HH; k++) {
        const float yv = y[k * BB + b].x;
        const float* wr = &Wsm[k * OO];
        #pragma unroll
        for (int o = 0; o < OO; o++) acc[o] += yv * wr[o];
    }

    float* op = out + (size_t)t * BB * OO + b * OO;
    #pragma unroll
    for (int o = 0; o < OO; o++) {
        const float x = acc[o];
        op[o] = fmaxf(x, 0.f) + log1pf(__expf(-fabsf(x)));  // stable softplus
    }
}

extern "C" void kernel_launch(void* const* d_in, const int* in_sizes, int n_in,
                              void* d_out, int out_size) {
    const float* x     = (const float*)d_in[0];
    const float* h0    = (const float*)d_in[1];   // (2,B,H)
    const float* c0    = (const float*)d_in[2];   // (2,B,H)
    const float* W_ih0 = (const float*)d_in[3];
    const float* W_hh0 = (const float*)d_in[4];
    const float* b_ih0 = (const float*)d_in[5];
    const float* b_hh0 = (const float*)d_in[6];
    const float* W_ih1 = (const float*)d_in[7];
    const float* W_hh1 = (const float*)d_in[8];
    const float* b_ih1 = (const float*)d_in[9];
    const float* b_hh1 = (const float*)d_in[10];
    const float* W_out = (const float*)d_in[11];
    const float* b_out = (const float*)d_in[12];

    float* out = (float*)d_out;
    float* hn  = out + (size_t)TT * BB * OO;   // (2,B,H)
    float* cn  = hn + 2 * BB * HH;             // (2,B,H)

    constexpr int KTOT0 = EE + HH;   // 314
    constexpr int KTOT1 = HH + HH;   // 512
    // L0: Ws + In2 + separate Part; L1: Ws + In2 (Part aliased)
    const int smem0 = KTOT0 * 64 * 4 + KTOT0 * 16 * 8 + 8 * 1024 * 4;  // 153,344
    const int smem1 = KTOT1 * 64 * 4 + KTOT1 * 16 * 8;                 // 196,608

    cudaFuncSetAttribute((const void*)lstm_layer_kernel<0>,
                         cudaFuncAttributeMaxDynamicSharedMemorySize, smem0);
    cudaFuncSetAttribute((const void*)lstm_layer_kernel<1>,
                         cudaFuncAttributeMaxDynamicSharedMemorySize, smem1);

    reset_kernel<<<1, 256>>>();

    lstm_layer_kernel<0><<<NCTA, NTHR, smem0>>>(
        x, W_ih0, W_hh0, b_ih0, b_hh0,
        h0 + 0 * BB * HH, c0 + 0 * BB * HH,
        hn + 0 * BB * HH, cn + 0 * BB * HH);

    lstm_layer_kernel<1><<<NCTA, NTHR, smem1>>>(
        nullptr, W_ih1, W_hh1, b_ih1, b_hh1,
        h0 + 1 * BB * HH, c0 + 1 * BB * HH,
        hn + 1 * BB * HH, cn + 1 * BB * HH);

    proj_kernel<<<TT, 128>>>(W_out, b_out, out);
}